// round 14
// baseline (speedup 1.0000x reference)
#include <cuda_runtime.h>
#include <cuda_bf16.h>
#include <cstdint>

#define NB   16384
#define RNN  256
#define LAT  64
#define ATT  64
#define NA   32
#define HID  256
#define NF   320   // 256 xh + 32 q + 32 score

// ======================= device globals =======================
__device__ __align__(16) float g_bias[NF];
__device__ __align__(16) __nv_bfloat16 g_Ah[(size_t)NB * RNN];
__device__ __align__(16) __nv_bfloat16 g_Al[(size_t)NB * RNN];
__device__ __align__(16) __nv_bfloat16 g_Bh[RNN * NF];
__device__ __align__(16) __nv_bfloat16 g_Bl[RNN * NF];
__device__ __align__(16) float g_Y[(size_t)NB * NF];          // only cols 256..319 used
__device__ __align__(16) __nv_bfloat16 g_Shi[(size_t)NB * HID]; // S' hi plane
__device__ __align__(16) __nv_bfloat16 g_Slo[(size_t)NB * HID]; // S' lo plane
__device__ __align__(16) float g_t[32 * HID];    // sorted thresholds [rank][h]
__device__ __align__(16) float g_K2[33 * HID];   // const term [rank][h]
__device__ __align__(16) __nv_bfloat16 g_w2h[HID * NA];  // w2^T hi [h][a]
__device__ __align__(16) __nv_bfloat16 g_w2l[HID * NA];  // w2^T lo [h][a]
__device__ __align__(16) float g_msb[NA];        // 32*b2

// ======================= asm helpers =======================
__device__ __forceinline__ uint32_t smem_u32(const void* p) {
    uint32_t a;
    asm("{ .reg .u64 t; cvta.to.shared.u64 t, %1; cvt.u32.u64 %0, t; }" : "=r"(a) : "l"(p));
    return a;
}
__device__ __forceinline__ void cp16(uint32_t dst, const void* src) {
    asm volatile("cp.async.ca.shared.global [%0], [%1], 16;" :: "r"(dst), "l"(src));
}
#define CP_COMMIT asm volatile("cp.async.commit_group;" ::: "memory")
#define CP_WAIT0  asm volatile("cp.async.wait_group 0;" ::: "memory")
#define CP_WAIT1  asm volatile("cp.async.wait_group 1;" ::: "memory")
#define CP_WAIT2  asm volatile("cp.async.wait_group 2;" ::: "memory")

__device__ __forceinline__ void ldsm_x4(uint32_t* r, uint32_t a) {
    asm volatile("ldmatrix.sync.aligned.m8n8.x4.shared.b16 {%0,%1,%2,%3}, [%4];"
        : "=r"(r[0]), "=r"(r[1]), "=r"(r[2]), "=r"(r[3]) : "r"(a));
}
__device__ __forceinline__ void ldsm_x4t(uint32_t* r, uint32_t a) {
    asm volatile("ldmatrix.sync.aligned.m8n8.x4.trans.shared.b16 {%0,%1,%2,%3}, [%4];"
        : "=r"(r[0]), "=r"(r[1]), "=r"(r[2]), "=r"(r[3]) : "r"(a));
}
__device__ __forceinline__ void mma16816(float* c, const uint32_t* a, const uint32_t* b) {
    asm volatile("mma.sync.aligned.m16n8k16.row.col.f32.bf16.bf16.f32 "
        "{%0,%1,%2,%3}, {%4,%5,%6,%7}, {%8,%9}, {%0,%1,%2,%3};"
        : "+f"(c[0]), "+f"(c[1]), "+f"(c[2]), "+f"(c[3])
        : "r"(a[0]), "r"(a[1]), "r"(a[2]), "r"(a[3]), "r"(b[0]), "r"(b[1]));
}
__device__ __forceinline__ uint32_t pack_bf2(float a, float b, float* ra, float* rb) {
    __nv_bfloat16 ha = __float2bfloat16_rn(a);
    __nv_bfloat16 hb = __float2bfloat16_rn(b);
    *ra = a - __bfloat162float(ha);
    *rb = b - __bfloat162float(hb);
    return (uint32_t)__bfloat16_as_ushort(ha) | ((uint32_t)__bfloat16_as_ushort(hb) << 16);
}

// ======================= K1: prep = B-pack/bias | sortprep | A-pack(ILP4+PRMT) =======================
#define APACK_QTR (NB * RNN / 8 / 4)   // 131072 chunks per quarter

__global__ void __launch_bounds__(256) prep_kernel(const float* __restrict__ h,
                                                   const float* __restrict__ act,
                                                   const float* __restrict__ qfw,
                                                   const float* __restrict__ qfb,
                                                   const float* __restrict__ w1,
                                                   const float* __restrict__ b1,
                                                   const float* __restrict__ w2,
                                                   const float* __restrict__ b2,
                                                   const float* __restrict__ kw,
                                                   const float* __restrict__ kb,
                                                   const float* __restrict__ qw,
                                                   const float* __restrict__ qb) {
    int tid = threadIdx.x;
    if (blockIdx.x < 320) {
        __shared__ float s_act[LAT];
        __shared__ float s_q[ATT];
        int j = blockIdx.x, k = tid;
        float v;
        if (j < 256) {
            v = w1[j * (RNN + LAT) + k];
        } else if (j < 288) {
            int a = j - 256;
            if (tid < LAT) s_act[tid] = act[a * LAT + tid];
            __syncthreads();
            v = 0.f;
#pragma unroll 8
            for (int l = 0; l < LAT; l++) v += s_act[l] * qfw[l * RNN + k];
        } else {
            int a = j - 288;
            if (tid < LAT) s_act[tid] = act[a * LAT + tid];
            __syncthreads();
            if (tid < ATT) {
                float q = qb[tid];
#pragma unroll 8
                for (int l = 0; l < LAT; l++) q += s_act[l] * qw[tid * LAT + l];
                s_q[tid] = q;
            }
            __syncthreads();
            v = 0.f;
#pragma unroll 8
            for (int t = 0; t < ATT; t++) v += s_q[t] * kw[t * RNN + k];
            v *= 0.125f;
        }
        __nv_bfloat16 hb = __float2bfloat16_rn(v);
        g_Bh[k * NF + j] = hb;
        g_Bl[k * NF + j] = __float2bfloat16_rn(v - __bfloat162float(hb));
        if (tid == 0) {
            float b = 0.f;
            if (j >= 256 && j < 288) {
                for (int l = 0; l < LAT; l++) b += s_act[l] * qfb[l];
            } else if (j >= 288) {
                for (int t = 0; t < ATT; t++) b += s_q[t] * kb[t];
                b *= 0.125f;
            }
            g_bias[j] = b;
        }
    } else if (blockIdx.x < 352) {
        // -------- sortprep --------
        __shared__ float s_actT[LAT * NA];
        __shared__ float s_v[8][NA];
        __shared__ float s_d[8][NA];
        int w = tid >> 5, lane = tid & 31;
        for (int i = tid; i < NA * LAT; i += 256) {
            int a = i >> 6, l = i & 63;
            s_actT[l * NA + a] = act[i];
        }
        __syncthreads();

        int hcol = (blockIdx.x - 320) * 8 + w;
        float val = b1[hcol];
#pragma unroll 8
        for (int l = 0; l < LAT; l++)
            val = fmaf(s_actT[l * NA + lane], w1[hcol * (RNN + LAT) + RNN + l], val);
        s_v[w][lane] = val;
        __syncwarp();
        int rank = 0;
#pragma unroll
        for (int b = 0; b < NA; b++) {
            float o = s_v[w][b];
            rank += (o > val) || (o == val && b < lane);
        }
        s_d[w][rank] = val;
        __syncwarp();
        float sv = s_d[w][lane];
        float incl = sv;
#pragma unroll
        for (int o = 1; o < 32; o <<= 1) {
            float u = __shfl_up_sync(0xffffffffu, incl, o);
            if (lane >= o) incl += u;
        }
        float excl = incl - sv;
        float ytot = __shfl_sync(0xffffffffu, incl, 31);
        g_t[lane * HID + hcol]  = -sv;
        g_K2[lane * HID + hcol] = fmaf(0.99f, excl, 0.01f * ytot);
        if (lane == 0) g_K2[32 * HID + hcol] = ytot;
        float wv = w2[lane * HID + hcol];
        __nv_bfloat16 wh = __float2bfloat16_rn(wv);
        g_w2h[hcol * NA + lane] = wh;
        g_w2l[hcol * NA + lane] = __float2bfloat16_rn(wv - __bfloat162float(wh));
        if (blockIdx.x == 320 && w == 0) g_msb[lane] = 32.f * b2[lane];
    } else {
        // -------- A-pack: 4 independent chunks, loads front-batched, PRMT-truncation convert --------
        int u0 = (blockIdx.x - 352) * 256 + tid;
        float4 va[8];
#pragma unroll
        for (int q = 0; q < 4; q++) {
            int u = u0 + q * APACK_QTR;
            const float4* src = (const float4*)&h[(size_t)(u >> 5) * RNN + (u & 31) * 8];
            va[2 * q]     = src[0];
            va[2 * q + 1] = src[1];
        }
#pragma unroll
        for (int q = 0; q < 4; q++) {
            int u = u0 + q * APACK_QTR;
            const float* f = (const float*)&va[2 * q];
            const uint32_t* ub = (const uint32_t*)&va[2 * q];
            uint32_t hw[4], lw[4];
#pragma unroll
            for (int i = 0; i < 4; i++) {
                uint32_t a = ub[2 * i], b = ub[2 * i + 1];
                hw[i] = __byte_perm(a, b, 0x7632);                       // top16(a)|top16(b)
                float la = f[2 * i]     - __uint_as_float(a & 0xFFFF0000u);
                float lb = f[2 * i + 1] - __uint_as_float(b & 0xFFFF0000u);
                lw[i] = __byte_perm(__float_as_uint(la), __float_as_uint(lb), 0x7632);
            }
            size_t off = (size_t)(u >> 5) * RNN + (u & 31) * 8;
            *(uint4*)&g_Ah[off] = make_uint4(hw[0], hw[1], hw[2], hw[3]);
            *(uint4*)&g_Al[off] = make_uint4(lw[0], lw[1], lw[2], lw[3]);
        }
    }
}

// ======================= K2: HMMA GEMM (3-stage pipeline) + fused leaky epilogue =======================
#define A_H  0
#define A_L  10240
#define B_H  20480
#define B_L  25088
#define BUFB 29696
#define TSTR 65
#define SM_T   (3 * BUFB)
#define SM_K2  (SM_T + 32 * TSTR * 4)
#define GEMM_SMEM (SM_K2 + 33 * TSTR * 4)

__global__ void __launch_bounds__(256, 2) gemm_mma_kernel() {
    extern __shared__ char gsm[];
    uint32_t sb = smem_u32(gsm);
    int tid = threadIdx.x;
    int lane = tid & 31, wid = tid >> 5;
    int wm = wid & 3, wn = wid >> 2;
    int m0 = blockIdx.y * 128;
    int n0 = blockIdx.x * 64;
    bool leakyBlk = (n0 < 256);

    if (leakyBlk) {
        float* st = (float*)(gsm + SM_T);
        float* sk = (float*)(gsm + SM_K2);
        for (int i = tid; i < 32 * 64; i += 256)
            st[(i >> 6) * TSTR + (i & 63)] = g_t[(i >> 6) * HID + n0 + (i & 63)];
        for (int i = tid; i < 33 * 64; i += 256)
            sk[(i >> 6) * TSTR + (i & 63)] = g_K2[(i >> 6) * HID + n0 + (i & 63)];
    }

    float acc[2][4][4];
#pragma unroll
    for (int mt = 0; mt < 2; mt++)
#pragma unroll
        for (int nt = 0; nt < 4; nt++)
#pragma unroll
            for (int i = 0; i < 4; i++) acc[mt][nt][i] = 0.f;

    auto load_tiles = [&](int it, int buf) {
        int k0 = it * 32;
        uint32_t base = sb + buf * BUFB;
#pragma unroll
        for (int i = 0; i < 2; i++) {
            int c = tid + 256 * i;
            int row = c >> 2, ch = c & 3;
            size_t src = (size_t)(m0 + row) * RNN + k0 + ch * 8;
            cp16(base + A_H + row * 80 + ch * 16, g_Ah + src);
            cp16(base + A_L + row * 80 + ch * 16, g_Al + src);
        }
        {
            int row = tid >> 3, ch = tid & 7;
            size_t src = (size_t)(k0 + row) * NF + n0 + ch * 8;
            cp16(base + B_H + row * 144 + ch * 16, g_Bh + src);
            cp16(base + B_L + row * 144 + ch * 16, g_Bl + src);
        }
    };

    auto compute = [&](int buf) {
        uint32_t base = sb + buf * BUFB;
#pragma unroll
        for (int ks = 0; ks < 32; ks += 16) {
            uint32_t ah[2][4], al[2][4], bh[2][4], bl[2][4];
            int arow = (lane & 7) + ((lane >> 3) & 1) * 8;
            int akk = ks + (lane >> 4) * 8;
#pragma unroll
            for (int mt = 0; mt < 2; mt++) {
                uint32_t ao = (wm * 32 + mt * 16 + arow) * 80 + akk * 2;
                ldsm_x4(ah[mt], base + A_H + ao);
                ldsm_x4(al[mt], base + A_L + ao);
            }
            int bk = ks + (lane & 7) + ((lane >> 3) & 1) * 8;
#pragma unroll
            for (int np = 0; np < 2; np++) {
                int bn = wn * 32 + np * 16 + ((lane >> 4) & 1) * 8;
                uint32_t bo = bk * 144 + bn * 2;
                ldsm_x4t(bh[np], base + B_H + bo);
                ldsm_x4t(bl[np], base + B_L + bo);
            }
#pragma unroll
            for (int mt = 0; mt < 2; mt++)
#pragma unroll
                for (int nt = 0; nt < 4; nt++) {
                    int np = nt >> 1, hf = nt & 1;
                    mma16816(acc[mt][nt], ah[mt], &bh[np][hf * 2]);
                    mma16816(acc[mt][nt], al[mt], &bh[np][hf * 2]);
                    mma16816(acc[mt][nt], ah[mt], &bl[np][hf * 2]);
                }
        }
    };

    load_tiles(0, 0);
    CP_COMMIT;
    load_tiles(1, 1);
    CP_COMMIT;
    for (int it = 0; it < 8; it++) {
        if (it + 2 < 8)      { load_tiles(it + 2, (it + 2) % 3); CP_COMMIT; CP_WAIT2; }
        else if (it + 1 < 8) { CP_WAIT1; }
        else                 { CP_WAIT0; }
        __syncthreads();
        compute(it % 3);
        __syncthreads();
    }

    if (leakyBlk) {
        const float* st = (const float*)(gsm + SM_T);
        const float* sk = (const float*)(gsm + SM_K2);
#pragma unroll
        for (int mt = 0; mt < 2; mt++) {
            int row = m0 + wm * 32 + mt * 16 + (lane >> 2);
#pragma unroll
            for (int nt = 0; nt < 4; nt++) {
                int cl0 = wn * 32 + nt * 8 + (lane & 3) * 2;
                float xs[4] = {acc[mt][nt][0], acc[mt][nt][1], acc[mt][nt][2], acc[mt][nt][3]};
                int cc[4] = {cl0, cl0 + 1, cl0, cl0 + 1};
                int lo[4] = {0, 0, 0, 0};
#pragma unroll
                for (int bb = 16; bb >= 1; bb >>= 1)
#pragma unroll
                    for (int v = 0; v < 4; v++)
                        lo[v] += (xs[v] >= st[(lo[v] + bb - 1) * TSTR + cc[v]]) ? bb : 0;
#pragma unroll
                for (int v = 0; v < 4; v++)
                    lo[v] += (xs[v] >= st[lo[v] * TSTR + cc[v]]) ? 1 : 0;
                float sp[4];
#pragma unroll
                for (int v = 0; v < 4; v++)
                    sp[v] = fmaf(xs[v], fmaf((float)lo[v], 0.99f, 0.32f), sk[lo[v] * TSTR + cc[v]]);
                int gc = n0 + cl0;
                float r0, r1, r2, r3;
                uint32_t hi01 = pack_bf2(sp[0], sp[1], &r0, &r1);
                uint32_t hi23 = pack_bf2(sp[2], sp[3], &r2, &r3);
                uint32_t lo01 = pack_bf2(r0, r1, &r0, &r1);
                uint32_t lo23 = pack_bf2(r2, r3, &r2, &r3);
                *(uint32_t*)&g_Shi[(size_t)row * HID + gc]       = hi01;
                *(uint32_t*)&g_Slo[(size_t)row * HID + gc]       = lo01;
                *(uint32_t*)&g_Shi[(size_t)(row + 8) * HID + gc] = hi23;
                *(uint32_t*)&g_Slo[(size_t)(row + 8) * HID + gc] = lo23;
            }
        }
    } else {
#pragma unroll
        for (int mt = 0; mt < 2; mt++) {
            int row = m0 + wm * 32 + mt * 16 + (lane >> 2);
#pragma unroll
            for (int nt = 0; nt < 4; nt++) {
                int col = n0 + wn * 32 + nt * 8 + (lane & 3) * 2;
                float bx = g_bias[col], by = g_bias[col + 1];
                float2 o0 = make_float2(acc[mt][nt][0] + bx, acc[mt][nt][1] + by);
                float2 o1 = make_float2(acc[mt][nt][2] + bx, acc[mt][nt][3] + by);
                *(float2*)&g_Y[(size_t)row * NF + col] = o0;
                *(float2*)&g_Y[(size_t)(row + 8) * NF + col] = o1;
            }
        }
    }
}

// ======================= K3: combine (BM=64, 128 thr, 3 CTA/SM) =======================
#define C_BUF 10240             // per A buffer: hi 5120 + lo 5120
#define C_BH  20480             // B hi plane: 256 rows * 80B
#define C_BL  (C_BH + 20480)
#define COMB_SMEM (C_BL + 20480)

__global__ void __launch_bounds__(128, 3) combine_kernel(float* __restrict__ out) {
    extern __shared__ char csm[];
    uint32_t sb = smem_u32(csm);
    __shared__ float s_msb[NA];
    int tid = threadIdx.x, lane = tid & 31, wid = tid >> 5;  // 4 warps
    int m0 = blockIdx.x * 64;
    if (tid < NA) s_msb[tid] = g_msb[tid];

    for (int i = tid; i < 1024; i += 128) {
        int row = i >> 2, ch = i & 3;
        cp16(sb + C_BH + row * 80 + ch * 16, g_w2h + row * 32 + ch * 8);
        cp16(sb + C_BL + row * 80 + ch * 16, g_w2l + row * 32 + ch * 8);
    }

    auto loadA = [&](int c, int buf) {
        int k0 = c * 32;
        uint32_t base = sb + buf * C_BUF;
#pragma unroll
        for (int i = tid; i < 256; i += 128) {
            int row = i >> 2, ch = i & 3;
            size_t src = (size_t)(m0 + row) * HID + k0 + ch * 8;
            cp16(base + row * 80 + ch * 16, g_Shi + src);
            cp16(base + 5120 + row * 80 + ch * 16, g_Slo + src);
        }
    };

    float acc[4][4];
#pragma unroll
    for (int nt = 0; nt < 4; nt++)
#pragma unroll
        for (int i = 0; i < 4; i++) acc[nt][i] = 0.f;

    loadA(0, 0);
    CP_COMMIT;
    for (int c = 0; c < 8; c++) {
        if (c + 1 < 8) { loadA(c + 1, (c + 1) & 1); CP_COMMIT; CP_WAIT1; }
        else           { CP_WAIT0; }
        __syncthreads();
        uint32_t abase = sb + (c & 1) * C_BUF;
#pragma unroll
        for (int ks = 0; ks < 32; ks += 16) {
            uint32_t ah[4], al[4], bh[2][4], bl[2][4];
            int arow = (lane & 7) + ((lane >> 3) & 1) * 8;
            int akk = ks + (lane >> 4) * 8;
            uint32_t ao = (wid * 16 + arow) * 80 + akk * 2;
            ldsm_x4(ah, abase + ao);
            ldsm_x4(al, abase + 5120 + ao);
            int bkg = c * 32 + ks + (lane & 7) + ((lane >> 3) & 1) * 8;
#pragma unroll
            for (int np = 0; np < 2; np++) {
                int bn = np * 16 + ((lane >> 4) & 1) * 8;
                uint32_t bo = bkg * 80 + bn * 2;
                ldsm_x4t(bh[np], sb + C_BH + bo);
                ldsm_x4t(bl[np], sb + C_BL + bo);
            }
#pragma unroll
            for (int nt = 0; nt < 4; nt++) {
                int np = nt >> 1, hf = nt & 1;
                mma16816(acc[nt], ah, &bh[np][hf * 2]);
                mma16816(acc[nt], al, &bh[np][hf * 2]);
                mma16816(acc[nt], ah, &bl[np][hf * 2]);
            }
        }
        __syncthreads();
    }

    int rbase = m0 + wid * 16 + (lane >> 2);
#pragma unroll
    for (int half = 0; half < 2; half++) {
        int row = rbase + half * 8;
        const float* Yr = g_Y + (size_t)row * NF;
        float qv[8], sc[8], mv[8];
#pragma unroll
        for (int nt = 0; nt < 4; nt++) {
            int col = nt * 8 + (lane & 3) * 2;
            float2 q2 = *(const float2*)&Yr[256 + col];
            float2 s2 = *(const float2*)&Yr[288 + col];
            qv[nt * 2] = q2.x; qv[nt * 2 + 1] = q2.y;
            sc[nt * 2] = s2.x; sc[nt * 2 + 1] = s2.y;
            mv[nt * 2]     = acc[nt][half * 2 + 0] + s_msb[col];
            mv[nt * 2 + 1] = acc[nt][half * 2 + 1] + s_msb[col + 1];
        }
        float mx = sc[0];
#pragma unroll
        for (int i = 1; i < 8; i++) mx = fmaxf(mx, sc[i]);
        mx = fmaxf(mx, __shfl_xor_sync(0xffffffffu, mx, 1));
        mx = fmaxf(mx, __shfl_xor_sync(0xffffffffu, mx, 2));
        float e[8], se = 0.f;
#pragma unroll
        for (int i = 0; i < 8; i++) { e[i] = __expf(sc[i] - mx); se += e[i]; }
        se += __shfl_xor_sync(0xffffffffu, se, 1);
        se += __shfl_xor_sync(0xffffffffu, se, 2);
        float inv = 1.f / se;
#pragma unroll
        for (int nt = 0; nt < 4; nt++) {
            int col = nt * 8 + (lane & 3) * 2;
            float2 o;
            o.x = qv[nt * 2]     + e[nt * 2]     * inv * mv[nt * 2];
            o.y = qv[nt * 2 + 1] + e[nt * 2 + 1] * inv * mv[nt * 2 + 1];
            *(float2*)&out[(size_t)row * NA + col] = o;
        }
    }
}

// ======================= launch =======================
extern "C" void kernel_launch(void* const* d_in, const int* in_sizes, int n_in,
                              void* d_out, int out_size) {
    const float* h   = (const float*)d_in[0];
    const float* act = (const float*)d_in[1];
    const float* qfw = (const float*)d_in[2];
    const float* qfb = (const float*)d_in[3];
    const float* w1  = (const float*)d_in[4];
    const float* b1  = (const float*)d_in[5];
    const float* w2  = (const float*)d_in[6];
    const float* b2  = (const float*)d_in[7];
    const float* kw  = (const float*)d_in[8];
    const float* kb  = (const float*)d_in[9];
    const float* qw  = (const float*)d_in[10];
    const float* qb  = (const float*)d_in[11];
    float* out = (float*)d_out;
    (void)in_sizes; (void)n_in; (void)out_size;

    cudaFuncSetAttribute(gemm_mma_kernel, cudaFuncAttributeMaxDynamicSharedMemorySize, GEMM_SMEM);
    cudaFuncSetAttribute(combine_kernel,  cudaFuncAttributeMaxDynamicSharedMemorySize, COMB_SMEM);

    prep_kernel<<<352 + APACK_QTR / 256, 256>>>(h, act, qfw, qfb, w1, b1, w2, b2, kw, kb, qw, qb);  // #0
    dim3 ggrid(NF / 64, NB / 128);
    gemm_mma_kernel<<<ggrid, 256, GEMM_SMEM>>>();                                                    // #1
    combine_kernel<<<NB / 64, 128, COMB_SMEM>>>(out);                                                // #2
}

// round 15
// speedup vs baseline: 1.3353x; 1.3353x over previous
#include <cuda_runtime.h>
#include <cuda_bf16.h>
#include <cstdint>

#define NB   16384
#define RNN  256
#define LAT  64
#define ATT  64
#define NA   32
#define HID  256
#define NF   320   // 256 xh + 32 q + 32 score

// ======================= device globals =======================
__device__ __align__(16) float g_bias[NF];
__device__ __align__(16) __nv_bfloat16 g_Bh[RNN * NF];
__device__ __align__(16) __nv_bfloat16 g_Bl[RNN * NF];
__device__ __align__(16) float g_Y[(size_t)NB * NF];          // only cols 256..319 used
__device__ __align__(16) __nv_bfloat16 g_Shi[(size_t)NB * HID]; // S' hi plane
__device__ __align__(16) __nv_bfloat16 g_Slo[(size_t)NB * HID]; // S' lo plane
__device__ __align__(16) float g_t[32 * HID];    // sorted thresholds [rank][h]
__device__ __align__(16) float g_K2[33 * HID];   // const term [rank][h]
__device__ __align__(16) __nv_bfloat16 g_w2h[HID * NA];  // w2^T hi [h][a]
__device__ __align__(16) __nv_bfloat16 g_w2l[HID * NA];  // w2^T lo [h][a]
__device__ __align__(16) float g_msb[NA];        // 32*b2

// ======================= asm helpers =======================
__device__ __forceinline__ uint32_t smem_u32(const void* p) {
    uint32_t a;
    asm("{ .reg .u64 t; cvta.to.shared.u64 t, %1; cvt.u32.u64 %0, t; }" : "=r"(a) : "l"(p));
    return a;
}
__device__ __forceinline__ void cp16(uint32_t dst, const void* src) {
    asm volatile("cp.async.ca.shared.global [%0], [%1], 16;" :: "r"(dst), "l"(src));
}
#define CP_COMMIT asm volatile("cp.async.commit_group;" ::: "memory")
#define CP_WAIT0  asm volatile("cp.async.wait_group 0;" ::: "memory")
#define CP_WAIT1  asm volatile("cp.async.wait_group 1;" ::: "memory")

__device__ __forceinline__ void ldsm_x4(uint32_t* r, uint32_t a) {
    asm volatile("ldmatrix.sync.aligned.m8n8.x4.shared.b16 {%0,%1,%2,%3}, [%4];"
        : "=r"(r[0]), "=r"(r[1]), "=r"(r[2]), "=r"(r[3]) : "r"(a));
}
__device__ __forceinline__ void ldsm_x4t(uint32_t* r, uint32_t a) {
    asm volatile("ldmatrix.sync.aligned.m8n8.x4.trans.shared.b16 {%0,%1,%2,%3}, [%4];"
        : "=r"(r[0]), "=r"(r[1]), "=r"(r[2]), "=r"(r[3]) : "r"(a));
}
__device__ __forceinline__ void mma16816(float* c, const uint32_t* a, const uint32_t* b) {
    asm volatile("mma.sync.aligned.m16n8k16.row.col.f32.bf16.bf16.f32 "
        "{%0,%1,%2,%3}, {%4,%5,%6,%7}, {%8,%9}, {%0,%1,%2,%3};"
        : "+f"(c[0]), "+f"(c[1]), "+f"(c[2]), "+f"(c[3])
        : "r"(a[0]), "r"(a[1]), "r"(a[2]), "r"(a[3]), "r"(b[0]), "r"(b[1]));
}
__device__ __forceinline__ uint32_t pack_bf2(float a, float b, float* ra, float* rb) {
    __nv_bfloat16 ha = __float2bfloat16_rn(a);
    __nv_bfloat16 hb = __float2bfloat16_rn(b);
    *ra = a - __bfloat162float(ha);
    *rb = b - __bfloat162float(hb);
    return (uint32_t)__bfloat16_as_ushort(ha) | ((uint32_t)__bfloat16_as_ushort(hb) << 16);
}

// ======================= K1: prep = B-pack/bias (0..319) | sortprep (320..351) =======================
__global__ void __launch_bounds__(256) prep_kernel(const float* __restrict__ act,
                                                   const float* __restrict__ qfw,
                                                   const float* __restrict__ qfb,
                                                   const float* __restrict__ w1,
                                                   const float* __restrict__ b1,
                                                   const float* __restrict__ w2,
                                                   const float* __restrict__ b2,
                                                   const float* __restrict__ kw,
                                                   const float* __restrict__ kb,
                                                   const float* __restrict__ qw,
                                                   const float* __restrict__ qb) {
    int tid = threadIdx.x;
    if (blockIdx.x < 320) {
        __shared__ float s_act[LAT];
        __shared__ float s_q[ATT];
        int j = blockIdx.x, k = tid;
        float v;
        if (j < 256) {
            v = w1[j * (RNN + LAT) + k];
        } else if (j < 288) {
            int a = j - 256;
            if (tid < LAT) s_act[tid] = act[a * LAT + tid];
            __syncthreads();
            v = 0.f;
#pragma unroll 8
            for (int l = 0; l < LAT; l++) v += s_act[l] * qfw[l * RNN + k];
        } else {
            int a = j - 288;
            if (tid < LAT) s_act[tid] = act[a * LAT + tid];
            __syncthreads();
            if (tid < ATT) {
                float q = qb[tid];
#pragma unroll 8
                for (int l = 0; l < LAT; l++) q += s_act[l] * qw[tid * LAT + l];
                s_q[tid] = q;
            }
            __syncthreads();
            v = 0.f;
#pragma unroll 8
            for (int t = 0; t < ATT; t++) v += s_q[t] * kw[t * RNN + k];
            v *= 0.125f;
        }
        __nv_bfloat16 hb = __float2bfloat16_rn(v);
        g_Bh[k * NF + j] = hb;
        g_Bl[k * NF + j] = __float2bfloat16_rn(v - __bfloat162float(hb));
        if (tid == 0) {
            float b = 0.f;
            if (j >= 256 && j < 288) {
                for (int l = 0; l < LAT; l++) b += s_act[l] * qfb[l];
            } else if (j >= 288) {
                for (int t = 0; t < ATT; t++) b += s_q[t] * kb[t];
                b *= 0.125f;
            }
            g_bias[j] = b;
        }
    } else {
        // -------- sortprep --------
        __shared__ float s_actT[LAT * NA];
        __shared__ float s_v[8][NA];
        __shared__ float s_d[8][NA];
        int w = tid >> 5, lane = tid & 31;
        for (int i = tid; i < NA * LAT; i += 256) {
            int a = i >> 6, l = i & 63;
            s_actT[l * NA + a] = act[i];
        }
        __syncthreads();

        int hcol = (blockIdx.x - 320) * 8 + w;
        float val = b1[hcol];
#pragma unroll 8
        for (int l = 0; l < LAT; l++)
            val = fmaf(s_actT[l * NA + lane], w1[hcol * (RNN + LAT) + RNN + l], val);
        s_v[w][lane] = val;
        __syncwarp();
        int rank = 0;
#pragma unroll
        for (int b = 0; b < NA; b++) {
            float o = s_v[w][b];
            rank += (o > val) || (o == val && b < lane);
        }
        s_d[w][rank] = val;
        __syncwarp();
        float sv = s_d[w][lane];
        float incl = sv;
#pragma unroll
        for (int o = 1; o < 32; o <<= 1) {
            float u = __shfl_up_sync(0xffffffffu, incl, o);
            if (lane >= o) incl += u;
        }
        float excl = incl - sv;
        float ytot = __shfl_sync(0xffffffffu, incl, 31);
        g_t[lane * HID + hcol]  = -sv;
        g_K2[lane * HID + hcol] = fmaf(0.99f, excl, 0.01f * ytot);
        if (lane == 0) g_K2[32 * HID + hcol] = ytot;
        float wv = w2[lane * HID + hcol];
        __nv_bfloat16 wh = __float2bfloat16_rn(wv);
        g_w2h[hcol * NA + lane] = wh;
        g_w2l[hcol * NA + lane] = __float2bfloat16_rn(wv - __bfloat162float(wh));
        if (blockIdx.x == 320 && w == 0) g_msb[lane] = 32.f * b2[lane];
    }
}

// ======================= K2: HMMA GEMM with in-kernel A conversion + fused leaky =======================
// smem: A double-buffered 128x32, hi+lo bf16 planes (80B row stride): ABUF=20480 each.
//       B double-buffered 32x64 hi+lo (144B row stride): BBUF=9216 each.
#define ABUF  20480
#define A_LO  10240
#define BBASE 40960
#define BBUF  9216
#define B_LO  4608
#define TSTR  65
#define SM_T   (BBASE + 2 * BBUF)          // 59392
#define SM_K2  (SM_T + 32 * TSTR * 4)      // +8320
#define GEMM_SMEM (SM_K2 + 33 * TSTR * 4 + 16)

__global__ void __launch_bounds__(256, 2) gemm_mma_kernel(const float* __restrict__ hmat) {
    extern __shared__ char gsm[];
    uint32_t sb = smem_u32(gsm);
    int tid = threadIdx.x;
    int lane = tid & 31, wid = tid >> 5;
    int wm = wid & 3, wn = wid >> 2;
    int m0 = blockIdx.y * 128;
    int n0 = blockIdx.x * 64;
    bool leakyBlk = (n0 < 256);

    if (leakyBlk) {
        float* st = (float*)(gsm + SM_T);
        float* sk = (float*)(gsm + SM_K2);
        for (int i = tid; i < 32 * 64; i += 256)
            st[(i >> 6) * TSTR + (i & 63)] = g_t[(i >> 6) * HID + n0 + (i & 63)];
        for (int i = tid; i < 33 * 64; i += 256)
            sk[(i >> 6) * TSTR + (i & 63)] = g_K2[(i >> 6) * HID + n0 + (i & 63)];
    }

    float acc[2][4][4];
#pragma unroll
    for (int mt = 0; mt < 2; mt++)
#pragma unroll
        for (int nt = 0; nt < 4; nt++)
#pragma unroll
            for (int i = 0; i < 4; i++) acc[mt][nt][i] = 0.f;

    int arow_g = tid >> 1, ahalf = tid & 1;     // A fp32 load mapping: 2 threads/row
    float4 va[4];
    auto ldgA = [&](int it) {
        const float4* src = (const float4*)&hmat[(size_t)(m0 + arow_g) * RNN + it * 32 + ahalf * 16];
        va[0] = src[0]; va[1] = src[1]; va[2] = src[2]; va[3] = src[3];
    };
    auto stsA = [&](int buf) {
        const float* f = (const float*)va;
        uint32_t hw[8], lw[8];
#pragma unroll
        for (int i = 0; i < 8; i++) {
            float la, lb;
            hw[i] = pack_bf2(f[2 * i], f[2 * i + 1], &la, &lb);
            float d0, d1;
            lw[i] = pack_bf2(la, lb, &d0, &d1);
        }
        char* p = gsm + buf * ABUF + arow_g * 80 + ahalf * 32;
        *(uint4*)(p)             = make_uint4(hw[0], hw[1], hw[2], hw[3]);
        *(uint4*)(p + 16)        = make_uint4(hw[4], hw[5], hw[6], hw[7]);
        *(uint4*)(p + A_LO)      = make_uint4(lw[0], lw[1], lw[2], lw[3]);
        *(uint4*)(p + A_LO + 16) = make_uint4(lw[4], lw[5], lw[6], lw[7]);
    };
    auto ldB = [&](int it, int buf) {
        int row = tid >> 3, ch = tid & 7;
        size_t src = (size_t)(it * 32 + row) * NF + n0 + ch * 8;
        uint32_t base = sb + BBASE + buf * BBUF;
        cp16(base + row * 144 + ch * 16, g_Bh + src);
        cp16(base + B_LO + row * 144 + ch * 16, g_Bl + src);
    };

    auto compute = [&](int buf) {
        uint32_t abase = sb + buf * ABUF;
        uint32_t bbase = sb + BBASE + buf * BBUF;
#pragma unroll
        for (int ks = 0; ks < 32; ks += 16) {
            uint32_t ah[2][4], al[2][4], bh[2][4], bl[2][4];
            int arow = (lane & 7) + ((lane >> 3) & 1) * 8;
            int akk = ks + (lane >> 4) * 8;
#pragma unroll
            for (int mt = 0; mt < 2; mt++) {
                uint32_t ao = (wm * 32 + mt * 16 + arow) * 80 + akk * 2;
                ldsm_x4(ah[mt], abase + ao);
                ldsm_x4(al[mt], abase + A_LO + ao);
            }
            int bk = ks + (lane & 7) + ((lane >> 3) & 1) * 8;
#pragma unroll
            for (int np = 0; np < 2; np++) {
                int bn = wn * 32 + np * 16 + ((lane >> 4) & 1) * 8;
                uint32_t bo = bk * 144 + bn * 2;
                ldsm_x4t(bh[np], bbase + bo);
                ldsm_x4t(bl[np], bbase + B_LO + bo);
            }
#pragma unroll
            for (int mt = 0; mt < 2; mt++)
#pragma unroll
                for (int nt = 0; nt < 4; nt++) {
                    int np = nt >> 1, hf = nt & 1;
                    mma16816(acc[mt][nt], ah[mt], &bh[np][hf * 2]);
                    mma16816(acc[mt][nt], al[mt], &bh[np][hf * 2]);
                    mma16816(acc[mt][nt], ah[mt], &bl[np][hf * 2]);
                }
        }
    };

    // pipeline: regs hold chunk it+1 fp32; smem double-buffers converted A + cp.async B
    ldgA(0);
    ldB(0, 0); CP_COMMIT;
    stsA(0);
    ldgA(1);
    ldB(1, 1); CP_COMMIT;
    for (int it = 0; it < 8; it++) {
        if (it < 7) { CP_WAIT1; } else { CP_WAIT0; }
        __syncthreads();
        compute(it & 1);
        __syncthreads();
        if (it + 1 < 8) {
            stsA((it + 1) & 1);
            if (it + 2 < 8) { ldgA(it + 2); ldB(it + 2, (it + 2) & 1); CP_COMMIT; }
        }
    }

    if (leakyBlk) {
        const float* st = (const float*)(gsm + SM_T);
        const float* sk = (const float*)(gsm + SM_K2);
#pragma unroll
        for (int mt = 0; mt < 2; mt++) {
            int row = m0 + wm * 32 + mt * 16 + (lane >> 2);
#pragma unroll
            for (int nt = 0; nt < 4; nt++) {
                int cl0 = wn * 32 + nt * 8 + (lane & 3) * 2;
                float xs[4] = {acc[mt][nt][0], acc[mt][nt][1], acc[mt][nt][2], acc[mt][nt][3]};
                int cc[4] = {cl0, cl0 + 1, cl0, cl0 + 1};
                int lo[4] = {0, 0, 0, 0};
#pragma unroll
                for (int bb = 16; bb >= 1; bb >>= 1)
#pragma unroll
                    for (int v = 0; v < 4; v++)
                        lo[v] += (xs[v] >= st[(lo[v] + bb - 1) * TSTR + cc[v]]) ? bb : 0;
#pragma unroll
                for (int v = 0; v < 4; v++)
                    lo[v] += (xs[v] >= st[lo[v] * TSTR + cc[v]]) ? 1 : 0;
                float sp[4];
#pragma unroll
                for (int v = 0; v < 4; v++)
                    sp[v] = fmaf(xs[v], fmaf((float)lo[v], 0.99f, 0.32f), sk[lo[v] * TSTR + cc[v]]);
                int gc = n0 + cl0;
                float r0, r1, r2, r3;
                uint32_t hi01 = pack_bf2(sp[0], sp[1], &r0, &r1);
                uint32_t hi23 = pack_bf2(sp[2], sp[3], &r2, &r3);
                uint32_t lo01 = pack_bf2(r0, r1, &r0, &r1);
                uint32_t lo23 = pack_bf2(r2, r3, &r2, &r3);
                *(uint32_t*)&g_Shi[(size_t)row * HID + gc]       = hi01;
                *(uint32_t*)&g_Slo[(size_t)row * HID + gc]       = lo01;
                *(uint32_t*)&g_Shi[(size_t)(row + 8) * HID + gc] = hi23;
                *(uint32_t*)&g_Slo[(size_t)(row + 8) * HID + gc] = lo23;
            }
        }
    } else {
#pragma unroll
        for (int mt = 0; mt < 2; mt++) {
            int row = m0 + wm * 32 + mt * 16 + (lane >> 2);
#pragma unroll
            for (int nt = 0; nt < 4; nt++) {
                int col = n0 + wn * 32 + nt * 8 + (lane & 3) * 2;
                float bx = g_bias[col], by = g_bias[col + 1];
                float2 o0 = make_float2(acc[mt][nt][0] + bx, acc[mt][nt][1] + by);
                float2 o1 = make_float2(acc[mt][nt][2] + bx, acc[mt][nt][3] + by);
                *(float2*)&g_Y[(size_t)row * NF + col] = o0;
                *(float2*)&g_Y[(size_t)(row + 8) * NF + col] = o1;
            }
        }
    }
}

// ======================= K3: combine (BM=64, 128 thr, 3 CTA/SM) =======================
#define C_BUF 10240             // per A buffer: hi 5120 + lo 5120
#define C_BH  20480             // B hi plane: 256 rows * 80B
#define C_BL  (C_BH + 20480)
#define COMB_SMEM (C_BL + 20480)

__global__ void __launch_bounds__(128, 3) combine_kernel(float* __restrict__ out) {
    extern __shared__ char csm[];
    uint32_t sb = smem_u32(csm);
    __shared__ float s_msb[NA];
    int tid = threadIdx.x, lane = tid & 31, wid = tid >> 5;  // 4 warps
    int m0 = blockIdx.x * 64;
    if (tid < NA) s_msb[tid] = g_msb[tid];

    for (int i = tid; i < 1024; i += 128) {
        int row = i >> 2, ch = i & 3;
        cp16(sb + C_BH + row * 80 + ch * 16, g_w2h + row * 32 + ch * 8);
        cp16(sb + C_BL + row * 80 + ch * 16, g_w2l + row * 32 + ch * 8);
    }

    auto loadA = [&](int c, int buf) {
        int k0 = c * 32;
        uint32_t base = sb + buf * C_BUF;
#pragma unroll
        for (int i = tid; i < 256; i += 128) {
            int row = i >> 2, ch = i & 3;
            size_t src = (size_t)(m0 + row) * HID + k0 + ch * 8;
            cp16(base + row * 80 + ch * 16, g_Shi + src);
            cp16(base + 5120 + row * 80 + ch * 16, g_Slo + src);
        }
    };

    float acc[4][4];
#pragma unroll
    for (int nt = 0; nt < 4; nt++)
#pragma unroll
        for (int i = 0; i < 4; i++) acc[nt][i] = 0.f;

    loadA(0, 0);
    CP_COMMIT;
    for (int c = 0; c < 8; c++) {
        if (c + 1 < 8) { loadA(c + 1, (c + 1) & 1); CP_COMMIT; CP_WAIT1; }
        else           { CP_WAIT0; }
        __syncthreads();
        uint32_t abase = sb + (c & 1) * C_BUF;
#pragma unroll
        for (int ks = 0; ks < 32; ks += 16) {
            uint32_t ah[4], al[4], bh[2][4], bl[2][4];
            int arow = (lane & 7) + ((lane >> 3) & 1) * 8;
            int akk = ks + (lane >> 4) * 8;
            uint32_t ao = (wid * 16 + arow) * 80 + akk * 2;
            ldsm_x4(ah, abase + ao);
            ldsm_x4(al, abase + 5120 + ao);
            int bkg = c * 32 + ks + (lane & 7) + ((lane >> 3) & 1) * 8;
#pragma unroll
            for (int np = 0; np < 2; np++) {
                int bn = np * 16 + ((lane >> 4) & 1) * 8;
                uint32_t bo = bkg * 80 + bn * 2;
                ldsm_x4t(bh[np], sb + C_BH + bo);
                ldsm_x4t(bl[np], sb + C_BL + bo);
            }
#pragma unroll
            for (int nt = 0; nt < 4; nt++) {
                int np = nt >> 1, hf = nt & 1;
                mma16816(acc[nt], ah, &bh[np][hf * 2]);
                mma16816(acc[nt], al, &bh[np][hf * 2]);
                mma16816(acc[nt], ah, &bl[np][hf * 2]);
            }
        }
        __syncthreads();
    }

    int rbase = m0 + wid * 16 + (lane >> 2);
#pragma unroll
    for (int half = 0; half < 2; half++) {
        int row = rbase + half * 8;
        const float* Yr = g_Y + (size_t)row * NF;
        float qv[8], sc[8], mv[8];
#pragma unroll
        for (int nt = 0; nt < 4; nt++) {
            int col = nt * 8 + (lane & 3) * 2;
            float2 q2 = *(const float2*)&Yr[256 + col];
            float2 s2 = *(const float2*)&Yr[288 + col];
            qv[nt * 2] = q2.x; qv[nt * 2 + 1] = q2.y;
            sc[nt * 2] = s2.x; sc[nt * 2 + 1] = s2.y;
            mv[nt * 2]     = acc[nt][half * 2 + 0] + s_msb[col];
            mv[nt * 2 + 1] = acc[nt][half * 2 + 1] + s_msb[col + 1];
        }
        float mx = sc[0];
#pragma unroll
        for (int i = 1; i < 8; i++) mx = fmaxf(mx, sc[i]);
        mx = fmaxf(mx, __shfl_xor_sync(0xffffffffu, mx, 1));
        mx = fmaxf(mx, __shfl_xor_sync(0xffffffffu, mx, 2));
        float e[8], se = 0.f;
#pragma unroll
        for (int i = 0; i < 8; i++) { e[i] = __expf(sc[i] - mx); se += e[i]; }
        se += __shfl_xor_sync(0xffffffffu, se, 1);
        se += __shfl_xor_sync(0xffffffffu, se, 2);
        float inv = 1.f / se;
#pragma unroll
        for (int nt = 0; nt < 4; nt++) {
            int col = nt * 8 + (lane & 3) * 2;
            float2 o;
            o.x = qv[nt * 2]     + e[nt * 2]     * inv * mv[nt * 2];
            o.y = qv[nt * 2 + 1] + e[nt * 2 + 1] * inv * mv[nt * 2 + 1];
            *(float2*)&out[(size_t)row * NA + col] = o;
        }
    }
}

// ======================= launch =======================
extern "C" void kernel_launch(void* const* d_in, const int* in_sizes, int n_in,
                              void* d_out, int out_size) {
    const float* h   = (const float*)d_in[0];
    const float* act = (const float*)d_in[1];
    const float* qfw = (const float*)d_in[2];
    const float* qfb = (const float*)d_in[3];
    const float* w1  = (const float*)d_in[4];
    const float* b1  = (const float*)d_in[5];
    const float* w2  = (const float*)d_in[6];
    const float* b2  = (const float*)d_in[7];
    const float* kw  = (const float*)d_in[8];
    const float* kb  = (const float*)d_in[9];
    const float* qw  = (const float*)d_in[10];
    const float* qb  = (const float*)d_in[11];
    float* out = (float*)d_out;
    (void)in_sizes; (void)n_in; (void)out_size;

    cudaFuncSetAttribute(gemm_mma_kernel, cudaFuncAttributeMaxDynamicSharedMemorySize, GEMM_SMEM);
    cudaFuncSetAttribute(combine_kernel,  cudaFuncAttributeMaxDynamicSharedMemorySize, COMB_SMEM);

    prep_kernel<<<352, 256>>>(act, qfw, qfb, w1, b1, w2, b2, kw, kb, qw, qb);  // #0
    dim3 ggrid(NF / 64, NB / 128);
    gemm_mma_kernel<<<ggrid, 256, GEMM_SMEM>>>(h);                              // #1
    combine_kernel<<<NB / 64, 128, COMB_SMEM>>>(out);                           // #2
}